// round 2
// baseline (speedup 1.0000x reference)
#include <cuda_runtime.h>

// LossFunction: fused IoU + smooth-L1 multi-loss over (B=256, N=8192, F=13).
// HBM-bound streaming reduction. SMEM staging for coalesced loads of the
// awkward 13-float rows; one atomicAdd per block.

#define F 13
#define ROWS_PER_BLOCK 256
#define THREADS 256

__device__ __forceinline__ float huber(float a, float b) {
    float d = fabsf(a - b);
    return d < 1.0f ? 0.5f * d * d : d - 0.5f;
}

__global__ void init_out_kernel(float* out) {
    out[0] = 0.0f;
}

__global__ __launch_bounds__(THREADS)
void loss_kernel(const float* __restrict__ tg,
                 const float* __restrict__ pr,
                 float* __restrict__ out,
                 long long rows,
                 float c1, float c2, float c3, float c4) {
    __shared__ float st[ROWS_PER_BLOCK * F];
    __shared__ float sp[ROWS_PER_BLOCK * F];

    long long row0 = (long long)blockIdx.x * ROWS_PER_BLOCK;
    long long rem  = rows - row0;
    int nrows = rem < ROWS_PER_BLOCK ? (int)rem : ROWS_PER_BLOCK;
    int nflt  = nrows * F;

    // Coalesced staging. Block base offset = row0*13 floats = row0*52 bytes;
    // with ROWS_PER_BLOCK=256, block base is 16B-aligned (3328 floats % 4 == 0).
    const float* tbase = tg + row0 * F;
    const float* pbase = pr + row0 * F;

    if (nrows == ROWS_PER_BLOCK) {
        // full block: float4 path (832 float4 per tensor)
        const float4* t4 = (const float4*)tbase;
        const float4* p4 = (const float4*)pbase;
        float4* st4 = (float4*)st;
        float4* sp4 = (float4*)sp;
        const int nf4 = ROWS_PER_BLOCK * F / 4;  // 832
        #pragma unroll
        for (int i = threadIdx.x; i < nf4; i += THREADS) {
            st4[i] = t4[i];
            sp4[i] = p4[i];
        }
    } else {
        for (int i = threadIdx.x; i < nflt; i += THREADS) {
            st[i] = tbase[i];
            sp[i] = pbase[i];
        }
    }
    __syncthreads();

    float acc = 0.0f;
    int r = threadIdx.x;
    if (r < nrows) {
        // Row loads: smem[r*13 + f] — 13 coprime with 32 banks => conflict-free.
        float tb[F], pb[F];
        #pragma unroll
        for (int f = 0; f < F; f++) {
            tb[f] = st[r * F + f];
            pb[f] = sp[r * F + f];
        }

        // loss2: smooth_l1 over first 4 features
        float s2 = 0.0f;
        #pragma unroll
        for (int f = 0; f < 4; f++) s2 += huber(tb[f], pb[f]);

        // loss4: smooth_l1 over features 4..11
        float s4 = 0.0f;
        #pragma unroll
        for (int f = 4; f < 12; f++) s4 += huber(tb[f], pb[f]);

        // loss3: last feature
        float s3 = huber(tb[12], pb[12]);

        // loss1: IoU vs 1
        float xx1 = fmaxf(tb[0], pb[0]);
        float yy1 = fmaxf(tb[1], pb[1]);
        float xx2 = fminf(tb[2], pb[2]);
        float yy2 = fminf(tb[3], pb[3]);
        float w = fmaxf(xx2 - xx1, 0.0f);
        float h = fmaxf(yy2 - yy1, 0.0f);
        float inter = w * h;
        float area1 = (tb[2] - tb[0]) * (tb[3] - tb[1]);
        float area2 = (pb[2] - pb[0]) * (pb[3] - pb[1]);
        float iou = inter / (area1 + area2 - inter + 1e-7f);
        float s1 = huber(1.0f, iou);

        acc = s1 * c1 + s2 * c2 + s3 * c3 + s4 * c4;
    }

    // warp shuffle reduce
    #pragma unroll
    for (int off = 16; off > 0; off >>= 1)
        acc += __shfl_xor_sync(0xFFFFFFFFu, acc, off);

    __shared__ float warp_part[THREADS / 32];
    int lane = threadIdx.x & 31;
    int wid  = threadIdx.x >> 5;
    if (lane == 0) warp_part[wid] = acc;
    __syncthreads();

    if (wid == 0) {
        float v = lane < (THREADS / 32) ? warp_part[lane] : 0.0f;
        #pragma unroll
        for (int off = 4; off > 0; off >>= 1)
            v += __shfl_xor_sync(0xFFFFFFFFu, v, off);
        if (lane == 0) atomicAdd(out, v);
    }
}

extern "C" void kernel_launch(void* const* d_in, const int* in_sizes, int n_in,
                              void* d_out, int out_size) {
    const float* targets = (const float*)d_in[0];
    const float* preds   = (const float*)d_in[1];
    float* out = (float*)d_out;

    long long total = (long long)in_sizes[0];
    long long rows  = total / F;  // B*N

    float inv = 1.0f / (float)rows;
    float c1 = inv;                 // loss1: mean over B*N
    float c2 = inv * 0.25f;         // loss2: mean over B*N*4
    float c3 = inv;                 // loss3: mean over B*N
    float c4 = 0.5f * inv * 0.125f; // loss4 * 0.5: mean over B*N*8

    int grid = (int)((rows + ROWS_PER_BLOCK - 1) / ROWS_PER_BLOCK);

    init_out_kernel<<<1, 1>>>(out);
    loss_kernel<<<grid, THREADS>>>(targets, preds, out, rows, c1, c2, c3, c4);
}

// round 3
// speedup vs baseline: 1.0007x; 1.0007x over previous
#include <cuda_runtime.h>

// LossFunction: fused IoU + smooth-L1 multi-loss over (B=256, N=8192, F=13).
// Pure HBM-bound streaming reduction.
//
// R2 change: elementwise losses (2,3,4) computed directly on the staged
// registers (no smem round-trip); smem holds ONLY the 4 box features per row
// for the IoU term. L1tex traffic per row: 104B LDG + 32B STS + 32B LDS
// (was 104 + 104 + 104).

#define F 13
#define ROWS_PER_BLOCK 1024
#define THREADS 256
// floats per block tile = ROWS_PER_BLOCK * F = 13312; float4s = 3328 = 13 * THREADS

__device__ __forceinline__ float huber(float a, float b) {
    float d = fabsf(a - b);
    return d < 1.0f ? 0.5f * d * d : d - 0.5f;
}

__global__ void init_out_kernel(float* out) {
    out[0] = 0.0f;
}

__global__ __launch_bounds__(THREADS)
void loss_kernel(const float* __restrict__ tg,
                 const float* __restrict__ pr,
                 float* __restrict__ out,
                 long long rows,
                 float c1, float c2, float c3, float c4) {
    // Box features only: 4 floats per row per tensor.
    __shared__ float st_box[ROWS_PER_BLOCK * 4];
    __shared__ float sp_box[ROWS_PER_BLOCK * 4];

    long long row0 = (long long)blockIdx.x * ROWS_PER_BLOCK;
    long long rem  = rows - row0;
    int nrows = rem < ROWS_PER_BLOCK ? (int)rem : ROWS_PER_BLOCK;

    const float* tbase = tg + row0 * F;   // row0*13 floats; row0 mult of 1024 -> 16B aligned
    const float* pbase = pr + row0 * F;

    float acc = 0.0f;

    if (nrows == ROWS_PER_BLOCK) {
        const float4* t4 = (const float4*)tbase;
        const float4* p4 = (const float4*)pbase;
        const int NF4 = ROWS_PER_BLOCK * F / 4;  // 3328 = 13 * THREADS
        #pragma unroll 13
        for (int i = threadIdx.x; i < NF4; i += THREADS) {
            float4 t = t4[i];
            float4 p = p4[i];
            int g = 4 * i;
            float tv[4] = {t.x, t.y, t.z, t.w};
            float pv[4] = {p.x, p.y, p.z, p.w};
            #pragma unroll
            for (int j = 0; j < 4; j++) {
                int gg  = g + j;
                int row = gg / F;            // const-div -> magic multiply
                int f   = gg - row * F;
                float wgt = (f < 4) ? c2 : ((f < 12) ? c4 : c3);
                acc += wgt * huber(tv[j], pv[j]);
                if (f < 4) {
                    st_box[row * 4 + f] = tv[j];
                    sp_box[row * 4 + f] = pv[j];
                }
            }
        }
    } else {
        // tail block (not hit for the benchmark shape, kept for generality)
        int nflt = nrows * F;
        for (int gg = threadIdx.x; gg < nflt; gg += THREADS) {
            float tv = tbase[gg];
            float pv = pbase[gg];
            int row = gg / F;
            int f   = gg - row * F;
            float wgt = (f < 4) ? c2 : ((f < 12) ? c4 : c3);
            acc += wgt * huber(tv, pv);
            if (f < 4) {
                st_box[row * 4 + f] = tv;
                sp_box[row * 4 + f] = pv;
            }
        }
    }
    __syncthreads();

    // IoU loss: one conflict-free LDS.128 per row per tensor.
    // Thread t handles rows t, t+256, t+512, t+768 -> lane-contiguous banks.
    for (int r = threadIdx.x; r < nrows; r += THREADS) {
        float4 tb = *(const float4*)&st_box[r * 4];
        float4 pb = *(const float4*)&sp_box[r * 4];
        float xx1 = fmaxf(tb.x, pb.x);
        float yy1 = fmaxf(tb.y, pb.y);
        float xx2 = fminf(tb.z, pb.z);
        float yy2 = fminf(tb.w, pb.w);
        float w = fmaxf(xx2 - xx1, 0.0f);
        float h = fmaxf(yy2 - yy1, 0.0f);
        float inter = w * h;
        float area1 = (tb.z - tb.x) * (tb.w - tb.y);
        float area2 = (pb.z - pb.x) * (pb.w - pb.y);
        float iou = inter / (area1 + area2 - inter + 1e-7f);
        acc += c1 * huber(1.0f, iou);
    }

    // block reduction
    #pragma unroll
    for (int off = 16; off > 0; off >>= 1)
        acc += __shfl_xor_sync(0xFFFFFFFFu, acc, off);

    __shared__ float warp_part[THREADS / 32];
    int lane = threadIdx.x & 31;
    int wid  = threadIdx.x >> 5;
    if (lane == 0) warp_part[wid] = acc;
    __syncthreads();

    if (wid == 0) {
        float v = lane < (THREADS / 32) ? warp_part[lane] : 0.0f;
        #pragma unroll
        for (int off = 4; off > 0; off >>= 1)
            v += __shfl_xor_sync(0xFFFFFFFFu, v, off);
        if (lane == 0) atomicAdd(out, v);
    }
}

extern "C" void kernel_launch(void* const* d_in, const int* in_sizes, int n_in,
                              void* d_out, int out_size) {
    const float* targets = (const float*)d_in[0];
    const float* preds   = (const float*)d_in[1];
    float* out = (float*)d_out;

    long long total = (long long)in_sizes[0];
    long long rows  = total / F;  // B*N = 2,097,152

    float inv = 1.0f / (float)rows;
    float c1 = inv;                 // loss1: mean over B*N
    float c2 = inv * 0.25f;         // loss2: mean over B*N*4
    float c3 = inv;                 // loss3: mean over B*N
    float c4 = 0.5f * inv * 0.125f; // loss4 * 0.5: mean over B*N*8

    int grid = (int)((rows + ROWS_PER_BLOCK - 1) / ROWS_PER_BLOCK);

    init_out_kernel<<<1, 1>>>(out);
    loss_kernel<<<grid, THREADS>>>(targets, preds, out, rows, c1, c2, c3, c4);
}